// round 4
// baseline (speedup 1.0000x reference)
#include <cuda_runtime.h>
#include <math.h>

// Problem constants
#define ETOT 1024
#define NTOK 8192
#define SEQ  2048
#define NH   16
#define HD   64
#define MLPD 4096

// Scratch (allocation-free rule: __device__ globals)
__device__ float g_h[NTOK * ETOT];        // LN output (reused for ln1/ln2)
__device__ float g_qkv[NTOK * 3 * ETOT];  // qkv projections
__device__ float g_attn[NTOK * ETOT];     // attention output
__device__ float g_x2[NTOK * ETOT];       // residual after attn sublayer
__device__ float g_mid[NTOK * MLPD];      // MLP hidden

// ---------------------------------------------------------------------------
// LayerNorm: one block per row (1024 elems), 256 threads
// ---------------------------------------------------------------------------
__global__ __launch_bounds__(256) void ln_kernel(
    const float* __restrict__ x, const float* __restrict__ g,
    const float* __restrict__ b, float* __restrict__ out)
{
    const int row = blockIdx.x;
    const float* xr = x + (long)row * ETOT;
    float v[4];
    float s = 0.f, s2 = 0.f;
#pragma unroll
    for (int i = 0; i < 4; i++) {
        v[i] = xr[threadIdx.x + i * 256];
        s += v[i];
        s2 += v[i] * v[i];
    }
    // warp reduce
#pragma unroll
    for (int o = 16; o; o >>= 1) {
        s  += __shfl_down_sync(0xffffffffu, s, o);
        s2 += __shfl_down_sync(0xffffffffu, s2, o);
    }
    __shared__ float sm[8], sm2[8];
    if ((threadIdx.x & 31) == 0) {
        sm[threadIdx.x >> 5] = s;
        sm2[threadIdx.x >> 5] = s2;
    }
    __syncthreads();
    float ts = 0.f, ts2 = 0.f;
#pragma unroll
    for (int i = 0; i < 8; i++) { ts += sm[i]; ts2 += sm2[i]; }
    const float mu = ts * (1.0f / ETOT);
    const float var = ts2 * (1.0f / ETOT) - mu * mu;
    const float r = rsqrtf(var + 1e-5f);
    float* orow = out + (long)row * ETOT;
#pragma unroll
    for (int i = 0; i < 4; i++) {
        int c = threadIdx.x + i * 256;
        orow[c] = (v[i] - mu) * r * g[c] + b[c];
    }
}

// ---------------------------------------------------------------------------
// SGEMM: C[M,N] = A[M,K] @ W[N,K]^T (+bias) (+GELU) (+residual)
// 128x128x8 tiling, 256 threads, 8x8 per thread
// ---------------------------------------------------------------------------
template <bool BIAS, bool RES, bool GELU>
__global__ __launch_bounds__(256) void sgemm(
    const float* __restrict__ A, const float* __restrict__ W,
    const float* __restrict__ bias, const float* __restrict__ res,
    float* __restrict__ C, int M, int N, int K)
{
    __shared__ float As[8][128];
    __shared__ float Ws[8][128];

    const int tid = threadIdx.x;
    const int m0 = blockIdx.y * 128;
    const int n0 = blockIdx.x * 128;
    const int tx = tid & 15;
    const int ty = tid >> 4;

    const int lr = tid >> 1;          // 0..127
    const int lc = (tid & 1) * 4;     // 0 or 4

    const float* Aptr = A + (long)(m0 + lr) * K + lc;
    const float* Wptr = W + (long)(n0 + lr) * K + lc;

    float acc[8][8];
#pragma unroll
    for (int i = 0; i < 8; i++)
#pragma unroll
        for (int j = 0; j < 8; j++) acc[i][j] = 0.f;

    for (int kt = 0; kt < K; kt += 8) {
        float4 av = *(const float4*)(Aptr + kt);
        float4 wv = *(const float4*)(Wptr + kt);
        As[lc + 0][lr] = av.x; As[lc + 1][lr] = av.y;
        As[lc + 2][lr] = av.z; As[lc + 3][lr] = av.w;
        Ws[lc + 0][lr] = wv.x; Ws[lc + 1][lr] = wv.y;
        Ws[lc + 2][lr] = wv.z; Ws[lc + 3][lr] = wv.w;
        __syncthreads();
#pragma unroll
        for (int kk = 0; kk < 8; kk++) {
            float ra[8], rb[8];
#pragma unroll
            for (int i = 0; i < 8; i++) ra[i] = As[kk][ty * 8 + i];
#pragma unroll
            for (int j = 0; j < 8; j++) rb[j] = Ws[kk][tx * 8 + j];
#pragma unroll
            for (int i = 0; i < 8; i++)
#pragma unroll
                for (int j = 0; j < 8; j++)
                    acc[i][j] += ra[i] * rb[j];
        }
        __syncthreads();
    }

#pragma unroll
    for (int i = 0; i < 8; i++) {
        const int m = m0 + ty * 8 + i;
#pragma unroll
        for (int j = 0; j < 8; j++) {
            const int n = n0 + tx * 8 + j;
            float v = acc[i][j];
            if (BIAS) v += bias[n];
            if (GELU) v = 0.5f * v * (1.0f + erff(v * 0.70710678118654752f));
            if (RES)  v += res[(long)m * N + n];
            C[(long)m * N + n] = v;
        }
    }
}

// ---------------------------------------------------------------------------
// Flash-style attention (fp32, online softmax)
// grid = (SEQ/64, B*H), block = 256
// qkv layout per token: [3][H][D] -> col = sel*1024 + h*64 + d
// out layout per token: [H][D]    -> col = h*64 + d
// ---------------------------------------------------------------------------
#define BQ 64
#define BKV 32

__global__ __launch_bounds__(256) void attn_kernel(
    const float* __restrict__ qkv, float* __restrict__ out)
{
    const int bh = blockIdx.y;
    const int b = bh >> 4;
    const int h = bh & 15;
    const int q0 = blockIdx.x * BQ;
    const int tid = threadIdx.x;
    const int tx = tid & 15;
    const int ty = tid >> 4;

    __shared__ float Qs[BQ][HD];        // q-major
    __shared__ float Kt[HD][BKV + 1];   // d-major (padded)
    __shared__ float Vs[BKV][HD];       // k-major
    __shared__ float Ps[BQ][BKV + 1];   // padded
    __shared__ float rowM[BQ], rowL[BQ], rowC[BQ];

    const int base = b * SEQ * 3 * ETOT;

    // load Q tile
    for (int idx = tid; idx < BQ * HD; idx += 256) {
        const int q = idx >> 6, d = idx & 63;
        Qs[q][d] = qkv[base + (q0 + q) * (3 * ETOT) + h * HD + d];
    }
    if (tid < BQ) { rowM[tid] = -1e30f; rowL[tid] = 0.f; }

    float acc[4][4];
#pragma unroll
    for (int i = 0; i < 4; i++)
#pragma unroll
        for (int j = 0; j < 4; j++) acc[i][j] = 0.f;

    __syncthreads();

    for (int k0 = 0; k0 < SEQ; k0 += BKV) {
        // load K (d-major) and V (k-major)
        for (int idx = tid; idx < BKV * HD; idx += 256) {
            const int k = idx >> 6, d = idx & 63;
            const int roff = base + (k0 + k) * (3 * ETOT) + h * HD + d;
            Kt[d][k] = qkv[roff + ETOT];
            Vs[k][d] = qkv[roff + 2 * ETOT];
        }
        __syncthreads();

        // S = Q K^T * scale : per thread 4 q-rows x 2 k-cols
        float s0[4], s1[4];
#pragma unroll
        for (int i = 0; i < 4; i++) { s0[i] = 0.f; s1[i] = 0.f; }
        for (int d = 0; d < HD; d++) {
            const float kv0 = Kt[d][tx * 2 + 0];
            const float kv1 = Kt[d][tx * 2 + 1];
#pragma unroll
            for (int i = 0; i < 4; i++) {
                const float qv = Qs[ty * 4 + i][d];
                s0[i] += qv * kv0;
                s1[i] += qv * kv1;
            }
        }
#pragma unroll
        for (int i = 0; i < 4; i++) {
            Ps[ty * 4 + i][tx * 2 + 0] = s0[i] * 0.125f;
            Ps[ty * 4 + i][tx * 2 + 1] = s1[i] * 0.125f;
        }
        __syncthreads();

        // online softmax per row (threads 0..63)
        if (tid < BQ) {
            const float mOld = rowM[tid];
            float mx = mOld;
#pragma unroll 8
            for (int k = 0; k < BKV; k++) mx = fmaxf(mx, Ps[tid][k]);
            const float corr = __expf(mOld - mx);
            float sum = 0.f;
#pragma unroll 8
            for (int k = 0; k < BKV; k++) {
                const float p = __expf(Ps[tid][k] - mx);
                Ps[tid][k] = p;
                sum += p;
            }
            rowM[tid] = mx;
            rowL[tid] = rowL[tid] * corr + sum;
            rowC[tid] = corr;
        }
        __syncthreads();

        // O = O*corr + P @ V : thread owns q-rows ty*4+i, d-cols tx*4+j
#pragma unroll
        for (int i = 0; i < 4; i++) {
            const float c = rowC[ty * 4 + i];
#pragma unroll
            for (int j = 0; j < 4; j++) acc[i][j] *= c;
        }
        for (int kk = 0; kk < BKV; kk++) {
            float v0 = Vs[kk][tx * 4 + 0];
            float v1 = Vs[kk][tx * 4 + 1];
            float v2 = Vs[kk][tx * 4 + 2];
            float v3 = Vs[kk][tx * 4 + 3];
#pragma unroll
            for (int i = 0; i < 4; i++) {
                const float p = Ps[ty * 4 + i][kk];
                acc[i][0] += p * v0;
                acc[i][1] += p * v1;
                acc[i][2] += p * v2;
                acc[i][3] += p * v3;
            }
        }
        __syncthreads();
    }

    // write out (divide by l)
#pragma unroll
    for (int i = 0; i < 4; i++) {
        const float inv = 1.0f / rowL[ty * 4 + i];
        const int tok = b * SEQ + q0 + ty * 4 + i;
#pragma unroll
        for (int j = 0; j < 4; j++) {
            out[(long)tok * ETOT + h * HD + tx * 4 + j] = acc[i][j] * inv;
        }
    }
}

// ---------------------------------------------------------------------------
// Host launcher
// ---------------------------------------------------------------------------
extern "C" void kernel_launch(void* const* d_in, const int* in_sizes, int n_in,
                              void* d_out, int out_size)
{
    const float* x     = (const float*)d_in[0];
    const float* qkv_w = (const float*)d_in[1];
    const float* fc_w  = (const float*)d_in[2];
    const float* fc_b  = (const float*)d_in[3];
    const float* ln1_g = (const float*)d_in[4];
    const float* ln1_b = (const float*)d_in[5];
    const float* ln2_g = (const float*)d_in[6];
    const float* ln2_b = (const float*)d_in[7];
    const float* w1    = (const float*)d_in[8];
    const float* b1    = (const float*)d_in[9];
    const float* w2    = (const float*)d_in[10];
    const float* b2    = (const float*)d_in[11];
    float* out = (float*)d_out;

    void *ph, *pq, *pa, *px2, *pm;
    cudaGetSymbolAddress(&ph,  g_h);
    cudaGetSymbolAddress(&pq,  g_qkv);
    cudaGetSymbolAddress(&pa,  g_attn);
    cudaGetSymbolAddress(&px2, g_x2);
    cudaGetSymbolAddress(&pm,  g_mid);
    float* h    = (float*)ph;
    float* qkvb = (float*)pq;
    float* attn = (float*)pa;
    float* x2   = (float*)px2;
    float* mid  = (float*)pm;

    // 1. h = LN1(x)
    ln_kernel<<<NTOK, 256>>>(x, ln1_g, ln1_b, h);

    // 2. qkv = h @ qkv_w^T
    sgemm<false, false, false><<<dim3((3 * ETOT) / 128, NTOK / 128), 256>>>(
        h, qkv_w, nullptr, nullptr, qkvb, NTOK, 3 * ETOT, ETOT);

    // 3. attention
    attn_kernel<<<dim3(SEQ / BQ, 4 * NH), 256>>>(qkvb, attn);

    // 4. x2 = x + attn @ fc_w^T + fc_b
    sgemm<true, true, false><<<dim3(ETOT / 128, NTOK / 128), 256>>>(
        attn, fc_w, fc_b, x, x2, NTOK, ETOT, ETOT);

    // 5. h = LN2(x2)
    ln_kernel<<<NTOK, 256>>>(x2, ln2_g, ln2_b, h);

    // 6. mid = gelu(h @ w1^T + b1)
    sgemm<true, false, true><<<dim3(MLPD / 128, NTOK / 128), 256>>>(
        h, w1, b1, nullptr, mid, NTOK, MLPD, ETOT);

    // 7. out = x2 + mid @ w2^T + b2
    sgemm<true, true, false><<<dim3(ETOT / 128, NTOK / 128), 256>>>(
        mid, w2, b2, x2, out, NTOK, ETOT, MLPD);
}

// round 6
// speedup vs baseline: 1.9630x; 1.9630x over previous
#include <cuda_runtime.h>
#include <math.h>
#include <stdint.h>

// Problem constants
#define ETOT 1024
#define NTOK 8192
#define SEQ  2048
#define NH   16
#define HD   64
#define MLPD 4096

// GEMM tile config (mma.sync tf32)
#define BM 128
#define BN 128
#define BK 32
#define SPAD 36                        // padded row stride (floats)
#define SMEM_GEMM (2 * 128 * SPAD * 4) // As + Bs, single stage (36864 B)

// Scratch (allocation-free rule: __device__ globals)
__device__ float g_h[NTOK * ETOT];
__device__ float g_qkv[NTOK * 3 * ETOT];
__device__ float g_attn[NTOK * ETOT];
__device__ float g_x2[NTOK * ETOT];
__device__ float g_mid[NTOK * MLPD];

// ---------------------------------------------------------------------------
// Helpers
// ---------------------------------------------------------------------------
__device__ __forceinline__ uint32_t f2tf32(float x) {
    uint32_t r;
    asm("cvt.rna.tf32.f32 %0, %1;" : "=r"(r) : "f"(x));
    return r;
}

__device__ __forceinline__ void mma_tf32(float* d, const uint32_t* a,
                                         const uint32_t* b) {
    asm volatile(
        "mma.sync.aligned.m16n8k8.row.col.f32.tf32.tf32.f32 "
        "{%0,%1,%2,%3}, {%4,%5,%6,%7}, {%8,%9}, {%0,%1,%2,%3};"
        : "+f"(d[0]), "+f"(d[1]), "+f"(d[2]), "+f"(d[3])
        : "r"(a[0]), "r"(a[1]), "r"(a[2]), "r"(a[3]), "r"(b[0]), "r"(b[1]));
}

// ---------------------------------------------------------------------------
// LayerNorm: one block per row (1024 elems), 256 threads
// ---------------------------------------------------------------------------
__global__ __launch_bounds__(256) void ln_kernel(
    const float* __restrict__ x, const float* __restrict__ g,
    const float* __restrict__ b, float* __restrict__ out)
{
    const int row = blockIdx.x;
    const float* xr = x + (long)row * ETOT;
    float v[4];
    float s = 0.f, s2 = 0.f;
#pragma unroll
    for (int i = 0; i < 4; i++) {
        v[i] = xr[threadIdx.x + i * 256];
        s += v[i];
        s2 += v[i] * v[i];
    }
#pragma unroll
    for (int o = 16; o; o >>= 1) {
        s  += __shfl_down_sync(0xffffffffu, s, o);
        s2 += __shfl_down_sync(0xffffffffu, s2, o);
    }
    __shared__ float sm[8], sm2[8];
    if ((threadIdx.x & 31) == 0) {
        sm[threadIdx.x >> 5] = s;
        sm2[threadIdx.x >> 5] = s2;
    }
    __syncthreads();
    float ts = 0.f, ts2 = 0.f;
#pragma unroll
    for (int i = 0; i < 8; i++) { ts += sm[i]; ts2 += sm2[i]; }
    const float mu = ts * (1.0f / ETOT);
    const float var = ts2 * (1.0f / ETOT) - mu * mu;
    const float r = rsqrtf(var + 1e-5f);
    float* orow = out + (long)row * ETOT;
#pragma unroll
    for (int i = 0; i < 4; i++) {
        int c = threadIdx.x + i * 256;
        orow[c] = (v[i] - mu) * r * g[c] + b[c];
    }
}

// ---------------------------------------------------------------------------
// tf32 mma.sync GEMM: C[M,N] = A[M,K] @ W[N,K]^T (+bias)(+GELU)(+residual)
// BM=BN=128, BK=32, 8 warps (2x4), 64x32 per warp, m16n8k8 frags.
// Single smem stage; next-tile LDGs issued before compute (latency hidden).
// ---------------------------------------------------------------------------
template <bool BIAS, bool RES, bool GELU>
__global__ __launch_bounds__(256) void tc_gemm(
    const float* __restrict__ A, const float* __restrict__ W,
    const float* __restrict__ bias, const float* __restrict__ res,
    float* __restrict__ C, int M, int N, int K)
{
    extern __shared__ float smem[];
    float* As = smem;                  // [128][SPAD]
    float* Bs = smem + 128 * SPAD;     // [128][SPAD]

    const int tid = threadIdx.x;
    const int m0 = blockIdx.y * BM;
    const int n0 = blockIdx.x * BN;

    // Loader mapping: 128 rows x 32 cols, 4 rounds of 32 rows
    const int lrow = tid >> 3;         // 0..31
    const int lcol = (tid & 7) * 4;    // 0,4,...,28

    const float* Ap = A + (size_t)(m0 + lrow) * K + lcol;
    const float* Wp = W + (size_t)(n0 + lrow) * K + lcol;

    // Warp/fragment mapping
    const int wid = tid >> 5;
    const int lane = tid & 31;
    const int wm = (wid >> 2) * 64;    // warp m offset in tile
    const int wn = (wid & 3) * 32;     // warp n offset in tile
    const int g = lane >> 2;           // groupID
    const int cg = lane & 3;           // threadID_in_group

    float acc[4][4][4];
#pragma unroll
    for (int mi = 0; mi < 4; mi++)
#pragma unroll
        for (int nj = 0; nj < 4; nj++)
#pragma unroll
            for (int e = 0; e < 4; e++) acc[mi][nj][e] = 0.f;

    // Prologue: fetch tile 0
    float4 ra[4], rw[4];
#pragma unroll
    for (int it = 0; it < 4; it++) {
        ra[it] = *(const float4*)(Ap + (size_t)(it * 32) * K);
        rw[it] = *(const float4*)(Wp + (size_t)(it * 32) * K);
    }

    const int T = K / BK;
    for (int t = 0; t < T; t++) {
        // Store current tile to smem (with tf32 rounding)
#pragma unroll
        for (int it = 0; it < 4; it++) {
            uint4 ta, tw;
            ta.x = f2tf32(ra[it].x); ta.y = f2tf32(ra[it].y);
            ta.z = f2tf32(ra[it].z); ta.w = f2tf32(ra[it].w);
            tw.x = f2tf32(rw[it].x); tw.y = f2tf32(rw[it].y);
            tw.z = f2tf32(rw[it].z); tw.w = f2tf32(rw[it].w);
            const int r = lrow + it * 32;
            *(uint4*)(As + r * SPAD + lcol) = ta;
            *(uint4*)(Bs + r * SPAD + lcol) = tw;
        }
        __syncthreads();

        // Issue next tile's global loads (hidden under compute)
        if (t + 1 < T) {
            const int kt = (t + 1) * BK;
#pragma unroll
            for (int it = 0; it < 4; it++) {
                ra[it] = *(const float4*)(Ap + (size_t)(it * 32) * K + kt);
                rw[it] = *(const float4*)(Wp + (size_t)(it * 32) * K + kt);
            }
        }

        // Compute: 4 k-steps of 8
#pragma unroll
        for (int ks = 0; ks < 4; ks++) {
            const int k = ks * 8;
            uint32_t af[4][4];
#pragma unroll
            for (int mi = 0; mi < 4; mi++) {
                const int mb = wm + mi * 16;
                af[mi][0] = __float_as_uint(As[(mb + g)     * SPAD + k + cg]);
                af[mi][1] = __float_as_uint(As[(mb + g + 8) * SPAD + k + cg]);
                af[mi][2] = __float_as_uint(As[(mb + g)     * SPAD + k + cg + 4]);
                af[mi][3] = __float_as_uint(As[(mb + g + 8) * SPAD + k + cg + 4]);
            }
            uint32_t bf[4][2];
#pragma unroll
            for (int nj = 0; nj < 4; nj++) {
                const int nb = wn + nj * 8 + g;
                bf[nj][0] = __float_as_uint(Bs[nb * SPAD + k + cg]);
                bf[nj][1] = __float_as_uint(Bs[nb * SPAD + k + cg + 4]);
            }
#pragma unroll
            for (int mi = 0; mi < 4; mi++)
#pragma unroll
                for (int nj = 0; nj < 4; nj++)
                    mma_tf32(acc[mi][nj], af[mi], bf[nj]);
        }
        __syncthreads();
    }

    // Epilogue: c0,c1 -> row (g), cols 2cg,2cg+1 ; c2,c3 -> row (g+8)
#pragma unroll
    for (int mi = 0; mi < 4; mi++) {
        const int mA = m0 + wm + mi * 16 + g;
        const int mB = mA + 8;
#pragma unroll
        for (int nj = 0; nj < 4; nj++) {
            const int n = n0 + wn + nj * 8 + 2 * cg;
            float2 v0 = make_float2(acc[mi][nj][0], acc[mi][nj][1]);
            float2 v1 = make_float2(acc[mi][nj][2], acc[mi][nj][3]);
            if (BIAS) {
                const float b0 = bias[n], b1 = bias[n + 1];
                v0.x += b0; v0.y += b1;
                v1.x += b0; v1.y += b1;
            }
            if (GELU) {
                v0.x = 0.5f * v0.x * (1.0f + erff(v0.x * 0.70710678118654752f));
                v0.y = 0.5f * v0.y * (1.0f + erff(v0.y * 0.70710678118654752f));
                v1.x = 0.5f * v1.x * (1.0f + erff(v1.x * 0.70710678118654752f));
                v1.y = 0.5f * v1.y * (1.0f + erff(v1.y * 0.70710678118654752f));
            }
            if (RES) {
                const float2 r0 = *(const float2*)(res + (size_t)mA * N + n);
                const float2 r1 = *(const float2*)(res + (size_t)mB * N + n);
                v0.x += r0.x; v0.y += r0.y;
                v1.x += r1.x; v1.y += r1.y;
            }
            *(float2*)(C + (size_t)mA * N + n) = v0;
            *(float2*)(C + (size_t)mB * N + n) = v1;
        }
    }
}

// ---------------------------------------------------------------------------
// Flash-style attention (fp32, unchanged from passing R1)
// ---------------------------------------------------------------------------
#define BQ 64
#define BKV 32

__global__ __launch_bounds__(256) void attn_kernel(
    const float* __restrict__ qkv, float* __restrict__ out)
{
    const int bh = blockIdx.y;
    const int b = bh >> 4;
    const int h = bh & 15;
    const int q0 = blockIdx.x * BQ;
    const int tid = threadIdx.x;
    const int tx = tid & 15;
    const int ty = tid >> 4;

    __shared__ float Qs[BQ][HD];
    __shared__ float Kt[HD][BKV + 1];
    __shared__ float Vs[BKV][HD];
    __shared__ float Ps[BQ][BKV + 1];
    __shared__ float rowM[BQ], rowL[BQ], rowC[BQ];

    const int base = b * SEQ * 3 * ETOT;

    for (int idx = tid; idx < BQ * HD; idx += 256) {
        const int q = idx >> 6, d = idx & 63;
        Qs[q][d] = qkv[base + (q0 + q) * (3 * ETOT) + h * HD + d];
    }
    if (tid < BQ) { rowM[tid] = -1e30f; rowL[tid] = 0.f; }

    float acc[4][4];
#pragma unroll
    for (int i = 0; i < 4; i++)
#pragma unroll
        for (int j = 0; j < 4; j++) acc[i][j] = 0.f;

    __syncthreads();

    for (int k0 = 0; k0 < SEQ; k0 += BKV) {
        for (int idx = tid; idx < BKV * HD; idx += 256) {
            const int k = idx >> 6, d = idx & 63;
            const int roff = base + (k0 + k) * (3 * ETOT) + h * HD + d;
            Kt[d][k] = qkv[roff + ETOT];
            Vs[k][d] = qkv[roff + 2 * ETOT];
        }
        __syncthreads();

        float s0[4], s1[4];
#pragma unroll
        for (int i = 0; i < 4; i++) { s0[i] = 0.f; s1[i] = 0.f; }
        for (int d = 0; d < HD; d++) {
            const float kv0 = Kt[d][tx * 2 + 0];
            const float kv1 = Kt[d][tx * 2 + 1];
#pragma unroll
            for (int i = 0; i < 4; i++) {
                const float qv = Qs[ty * 4 + i][d];
                s0[i] += qv * kv0;
                s1[i] += qv * kv1;
            }
        }
#pragma unroll
        for (int i = 0; i < 4; i++) {
            Ps[ty * 4 + i][tx * 2 + 0] = s0[i] * 0.125f;
            Ps[ty * 4 + i][tx * 2 + 1] = s1[i] * 0.125f;
        }
        __syncthreads();

        if (tid < BQ) {
            const float mOld = rowM[tid];
            float mx = mOld;
#pragma unroll 8
            for (int k = 0; k < BKV; k++) mx = fmaxf(mx, Ps[tid][k]);
            const float corr = __expf(mOld - mx);
            float sum = 0.f;
#pragma unroll 8
            for (int k = 0; k < BKV; k++) {
                const float p = __expf(Ps[tid][k] - mx);
                Ps[tid][k] = p;
                sum += p;
            }
            rowM[tid] = mx;
            rowL[tid] = rowL[tid] * corr + sum;
            rowC[tid] = corr;
        }
        __syncthreads();

#pragma unroll
        for (int i = 0; i < 4; i++) {
            const float c = rowC[ty * 4 + i];
#pragma unroll
            for (int j = 0; j < 4; j++) acc[i][j] *= c;
        }
        for (int kk = 0; kk < BKV; kk++) {
            float v0 = Vs[kk][tx * 4 + 0];
            float v1 = Vs[kk][tx * 4 + 1];
            float v2 = Vs[kk][tx * 4 + 2];
            float v3 = Vs[kk][tx * 4 + 3];
#pragma unroll
            for (int i = 0; i < 4; i++) {
                const float p = Ps[ty * 4 + i][kk];
                acc[i][0] += p * v0;
                acc[i][1] += p * v1;
                acc[i][2] += p * v2;
                acc[i][3] += p * v3;
            }
        }
        __syncthreads();
    }

#pragma unroll
    for (int i = 0; i < 4; i++) {
        const float inv = 1.0f / rowL[ty * 4 + i];
        const int tok = b * SEQ + q0 + ty * 4 + i;
#pragma unroll
        for (int j = 0; j < 4; j++) {
            out[(long)tok * ETOT + h * HD + tx * 4 + j] = acc[i][j] * inv;
        }
    }
}

// ---------------------------------------------------------------------------
// Host launcher
// ---------------------------------------------------------------------------
extern "C" void kernel_launch(void* const* d_in, const int* in_sizes, int n_in,
                              void* d_out, int out_size)
{
    const float* x     = (const float*)d_in[0];
    const float* qkv_w = (const float*)d_in[1];
    const float* fc_w  = (const float*)d_in[2];
    const float* fc_b  = (const float*)d_in[3];
    const float* ln1_g = (const float*)d_in[4];
    const float* ln1_b = (const float*)d_in[5];
    const float* ln2_g = (const float*)d_in[6];
    const float* ln2_b = (const float*)d_in[7];
    const float* w1    = (const float*)d_in[8];
    const float* b1    = (const float*)d_in[9];
    const float* w2    = (const float*)d_in[10];
    const float* b2    = (const float*)d_in[11];
    float* out = (float*)d_out;

    void *ph, *pq, *pa, *px2, *pm;
    cudaGetSymbolAddress(&ph,  g_h);
    cudaGetSymbolAddress(&pq,  g_qkv);
    cudaGetSymbolAddress(&pa,  g_attn);
    cudaGetSymbolAddress(&px2, g_x2);
    cudaGetSymbolAddress(&pm,  g_mid);
    float* h    = (float*)ph;
    float* qkvb = (float*)pq;
    float* attn = (float*)pa;
    float* x2   = (float*)px2;
    float* mid  = (float*)pm;

    // 1. h = LN1(x)
    ln_kernel<<<NTOK, 256>>>(x, ln1_g, ln1_b, h);

    // 2. qkv = h @ qkv_w^T
    tc_gemm<false, false, false>
        <<<dim3((3 * ETOT) / BN, NTOK / BM), 256, SMEM_GEMM>>>(
        h, qkv_w, nullptr, nullptr, qkvb, NTOK, 3 * ETOT, ETOT);

    // 3. attention
    attn_kernel<<<dim3(SEQ / BQ, 4 * NH), 256>>>(qkvb, attn);

    // 4. x2 = x + attn @ fc_w^T + fc_b
    tc_gemm<true, true, false>
        <<<dim3(ETOT / BN, NTOK / BM), 256, SMEM_GEMM>>>(
        attn, fc_w, fc_b, x, x2, NTOK, ETOT, ETOT);

    // 5. h = LN2(x2)
    ln_kernel<<<NTOK, 256>>>(x2, ln2_g, ln2_b, h);

    // 6. mid = gelu(h @ w1^T + b1)
    tc_gemm<true, false, true>
        <<<dim3(MLPD / BN, NTOK / BM), 256, SMEM_GEMM>>>(
        h, w1, b1, nullptr, mid, NTOK, MLPD, ETOT);

    // 7. out = x2 + mid @ w2^T + b2
    tc_gemm<true, true, false>
        <<<dim3(ETOT / BN, NTOK / BM), 256, SMEM_GEMM>>>(
        mid, w2, b2, x2, out, NTOK, ETOT, MLPD);
}

// round 8
// speedup vs baseline: 3.6998x; 1.8848x over previous
#include <cuda_runtime.h>
#include <math.h>
#include <stdint.h>

// Problem constants
#define ETOT 1024
#define NTOK 8192
#define SEQ  2048
#define NH   16
#define HD   64
#define MLPD 4096

// GEMM tile config
#define BM 128
#define BN 128
#define BK 32
#define SPAD 36
#define STAGE_FLOATS (2 * 128 * SPAD)                  // As+Bs per stage
#define SMEM_GEMM (2 * STAGE_FLOATS * 4)               // 73728 B

// Attention config
#define AQ 128
#define AKV 64
#define APAD 76
#define SMEM_ATTN ((2 * AKV + AQ) * APAD * 4)          // 77824 B

// Scratch
__device__ float g_h[NTOK * ETOT];
__device__ float g_qkv[NTOK * 3 * ETOT];
__device__ float g_attn[NTOK * ETOT];
__device__ float g_x2[NTOK * ETOT];
__device__ float g_mid[NTOK * MLPD];
__device__ float g_wq[3 * ETOT * ETOT];   // rounded weights
__device__ float g_wf[ETOT * ETOT];
__device__ float g_w1[MLPD * ETOT];
__device__ float g_w2[ETOT * MLPD];

// ---------------------------------------------------------------------------
// Helpers
// ---------------------------------------------------------------------------
__device__ __forceinline__ uint32_t f2tf32(float x) {
    uint32_t r;
    asm("cvt.rna.tf32.f32 %0, %1;" : "=r"(r) : "f"(x));
    return r;
}

__device__ __forceinline__ float f2tf32f(float x) {
    return __uint_as_float(f2tf32(x));
}

__device__ __forceinline__ void mma_tf32(float* d, const uint32_t* a,
                                         const uint32_t* b) {
    asm volatile(
        "mma.sync.aligned.m16n8k8.row.col.f32.tf32.tf32.f32 "
        "{%0,%1,%2,%3}, {%4,%5,%6,%7}, {%8,%9}, {%0,%1,%2,%3};"
        : "+f"(d[0]), "+f"(d[1]), "+f"(d[2]), "+f"(d[3])
        : "r"(a[0]), "r"(a[1]), "r"(a[2]), "r"(a[3]), "r"(b[0]), "r"(b[1]));
}

__device__ __forceinline__ void cp16(uint32_t dst_smem, const float* src) {
    asm volatile("cp.async.cg.shared.global [%0], [%1], 16;"
                 :: "r"(dst_smem), "l"(src));
}

__device__ __forceinline__ uint32_t smem_u32(const void* p) {
    uint32_t a;
    asm("{ .reg .u64 t; cvta.to.shared.u64 t, %1; cvt.u32.u64 %0, t; }"
        : "=r"(a) : "l"(p));
    return a;
}

// ---------------------------------------------------------------------------
// Weight rounding: out[i] = tf32_rna(in[i]), vectorized
// ---------------------------------------------------------------------------
__global__ __launch_bounds__(256) void round_w(const float* __restrict__ in,
                                               float* __restrict__ out, int n4)
{
    const int i = blockIdx.x * 256 + threadIdx.x;
    if (i < n4) {
        float4 v = ((const float4*)in)[i];
        v.x = f2tf32f(v.x); v.y = f2tf32f(v.y);
        v.z = f2tf32f(v.z); v.w = f2tf32f(v.w);
        ((float4*)out)[i] = v;
    }
}

// ---------------------------------------------------------------------------
// LayerNorm (rounds output to tf32 — output only feeds mma)
// ---------------------------------------------------------------------------
__global__ __launch_bounds__(256) void ln_kernel(
    const float* __restrict__ x, const float* __restrict__ g,
    const float* __restrict__ b, float* __restrict__ out)
{
    const int row = blockIdx.x;
    const float* xr = x + (long)row * ETOT;
    float v[4];
    float s = 0.f, s2 = 0.f;
#pragma unroll
    for (int i = 0; i < 4; i++) {
        v[i] = xr[threadIdx.x + i * 256];
        s += v[i];
        s2 += v[i] * v[i];
    }
#pragma unroll
    for (int o = 16; o; o >>= 1) {
        s  += __shfl_down_sync(0xffffffffu, s, o);
        s2 += __shfl_down_sync(0xffffffffu, s2, o);
    }
    __shared__ float sm[8], sm2[8];
    if ((threadIdx.x & 31) == 0) {
        sm[threadIdx.x >> 5] = s;
        sm2[threadIdx.x >> 5] = s2;
    }
    __syncthreads();
    float ts = 0.f, ts2 = 0.f;
#pragma unroll
    for (int i = 0; i < 8; i++) { ts += sm[i]; ts2 += sm2[i]; }
    const float mu = ts * (1.0f / ETOT);
    const float var = ts2 * (1.0f / ETOT) - mu * mu;
    const float r = rsqrtf(var + 1e-5f);
    float* orow = out + (long)row * ETOT;
#pragma unroll
    for (int i = 0; i < 4; i++) {
        int c = threadIdx.x + i * 256;
        orow[c] = f2tf32f((v[i] - mu) * r * g[c] + b[c]);
    }
}

// ---------------------------------------------------------------------------
// tf32 GEMM, cp.async 2-stage pipeline. Inputs must be pre-rounded to tf32.
// ---------------------------------------------------------------------------
template <bool BIAS, bool RES, bool GELU, bool ROUND>
__global__ __launch_bounds__(256, 2) void tc_gemm(
    const float* __restrict__ A, const float* __restrict__ W,
    const float* __restrict__ bias, const float* __restrict__ res,
    float* __restrict__ C, int M, int N, int K)
{
    extern __shared__ float smem[];

    const int tid = threadIdx.x;
    const int m0 = blockIdx.y * BM;
    const int n0 = blockIdx.x * BN;

    const int lrow = tid >> 3;
    const int lcol = (tid & 7) * 4;

    const float* Ap = A + (size_t)(m0 + lrow) * K + lcol;
    const float* Wp = W + (size_t)(n0 + lrow) * K + lcol;

    const uint32_t sb = smem_u32(smem);

    const int wid = tid >> 5;
    const int lane = tid & 31;
    const int wm = (wid >> 2) * 64;
    const int wn = (wid & 3) * 32;
    const int g = lane >> 2;
    const int cg = lane & 3;

    float acc[4][4][4];
#pragma unroll
    for (int mi = 0; mi < 4; mi++)
#pragma unroll
        for (int nj = 0; nj < 4; nj++)
#pragma unroll
            for (int e = 0; e < 4; e++) acc[mi][nj][e] = 0.f;

    // stage issue: 8 cp.async per thread (4 rows A + 4 rows B)
    auto issue = [&](int st, int kt) {
        const uint32_t dA = sb + (uint32_t)(st * STAGE_FLOATS) * 4;
        const uint32_t dB = dA + 128 * SPAD * 4;
#pragma unroll
        for (int it = 0; it < 4; it++) {
            const uint32_t off = (uint32_t)((lrow + it * 32) * SPAD + lcol) * 4;
            cp16(dA + off, Ap + (size_t)(it * 32) * K + kt);
            cp16(dB + off, Wp + (size_t)(it * 32) * K + kt);
        }
        asm volatile("cp.async.commit_group;");
    };

    issue(0, 0);

    const int T = K / BK;
    for (int t = 0; t < T; t++) {
        if (t + 1 < T) {
            issue((t + 1) & 1, (t + 1) * BK);
            asm volatile("cp.async.wait_group 1;");
        } else {
            asm volatile("cp.async.wait_group 0;");
        }
        __syncthreads();

        const float* As = smem + (t & 1) * STAGE_FLOATS;
        const float* Bs = As + 128 * SPAD;

#pragma unroll
        for (int ks = 0; ks < 4; ks++) {
            const int k = ks * 8;
            uint32_t af[4][4];
#pragma unroll
            for (int mi = 0; mi < 4; mi++) {
                const int mb = wm + mi * 16;
                af[mi][0] = __float_as_uint(As[(mb + g)     * SPAD + k + cg]);
                af[mi][1] = __float_as_uint(As[(mb + g + 8) * SPAD + k + cg]);
                af[mi][2] = __float_as_uint(As[(mb + g)     * SPAD + k + cg + 4]);
                af[mi][3] = __float_as_uint(As[(mb + g + 8) * SPAD + k + cg + 4]);
            }
            uint32_t bf[4][2];
#pragma unroll
            for (int nj = 0; nj < 4; nj++) {
                const int nb = wn + nj * 8 + g;
                bf[nj][0] = __float_as_uint(Bs[nb * SPAD + k + cg]);
                bf[nj][1] = __float_as_uint(Bs[nb * SPAD + k + cg + 4]);
            }
#pragma unroll
            for (int mi = 0; mi < 4; mi++)
#pragma unroll
                for (int nj = 0; nj < 4; nj++)
                    mma_tf32(acc[mi][nj], af[mi], bf[nj]);
        }
        __syncthreads();
    }

    // Epilogue
#pragma unroll
    for (int mi = 0; mi < 4; mi++) {
        const int mA = m0 + wm + mi * 16 + g;
        const int mB = mA + 8;
#pragma unroll
        for (int nj = 0; nj < 4; nj++) {
            const int n = n0 + wn + nj * 8 + 2 * cg;
            float2 v0 = make_float2(acc[mi][nj][0], acc[mi][nj][1]);
            float2 v1 = make_float2(acc[mi][nj][2], acc[mi][nj][3]);
            if (BIAS) {
                const float b0 = bias[n], b1 = bias[n + 1];
                v0.x += b0; v0.y += b1;
                v1.x += b0; v1.y += b1;
            }
            if (GELU) {
                v0.x = 0.5f * v0.x * (1.0f + erff(v0.x * 0.70710678118654752f));
                v0.y = 0.5f * v0.y * (1.0f + erff(v0.y * 0.70710678118654752f));
                v1.x = 0.5f * v1.x * (1.0f + erff(v1.x * 0.70710678118654752f));
                v1.y = 0.5f * v1.y * (1.0f + erff(v1.y * 0.70710678118654752f));
            }
            if (RES) {
                const float2 r0 = *(const float2*)(res + (size_t)mA * N + n);
                const float2 r1 = *(const float2*)(res + (size_t)mB * N + n);
                v0.x += r0.x; v0.y += r0.y;
                v1.x += r1.x; v1.y += r1.y;
            }
            if (ROUND) {
                v0.x = f2tf32f(v0.x); v0.y = f2tf32f(v0.y);
                v1.x = f2tf32f(v1.x); v1.y = f2tf32f(v1.y);
            }
            *(float2*)(C + (size_t)mA * N + n) = v0;
            *(float2*)(C + (size_t)mB * N + n) = v1;
        }
    }
}

// ---------------------------------------------------------------------------
// tf32 mma flash attention.
// grid = (SEQ/128, B*NH), 256 threads = 8 warps, each warp owns 16 q-rows.
// Q/K/V come pre-rounded to tf32 (GEMM2 epilogue). P rounded in-kernel.
// ---------------------------------------------------------------------------
__global__ __launch_bounds__(256, 2) void attn_mma(
    const float* __restrict__ qkv, float* __restrict__ out)
{
    extern __shared__ float asmem[];
    float* Ks = asmem;                     // [AKV][APAD]
    float* Vs = asmem + AKV * APAD;        // [AKV][APAD]
    float* Ps = asmem + 2 * AKV * APAD;    // [AQ][APAD] (also Q staging)

    const int bh = blockIdx.y;
    const int b = bh >> 4;
    const int h = bh & 15;
    const int q0 = blockIdx.x * AQ;
    const int tid = threadIdx.x;
    const int wid = tid >> 5;
    const int lane = tid & 31;
    const int g = lane >> 2;
    const int cg = lane & 3;
    const int wrow = wid * 16;

    const size_t base = (size_t)b * SEQ * 3 * ETOT;

    // Stage Q into Ps (coalesced float2)
    for (int idx = tid; idx < AQ * HD / 2; idx += 256) {
        const int r = idx >> 5;
        const int c = (idx & 31) * 2;
        const float2 qv = *(const float2*)(qkv + base + (size_t)(q0 + r) * (3 * ETOT) + h * HD + c);
        Ps[r * APAD + c] = qv.x;
        Ps[r * APAD + c + 1] = qv.y;
    }
    __syncthreads();

    // Load persistent Q fragments
    uint32_t qf[8][4];
#pragma unroll
    for (int ks = 0; ks < 8; ks++) {
        const int k = ks * 8;
        qf[ks][0] = __float_as_uint(Ps[(wrow + g)     * APAD + k + cg]);
        qf[ks][1] = __float_as_uint(Ps[(wrow + g + 8) * APAD + k + cg]);
        qf[ks][2] = __float_as_uint(Ps[(wrow + g)     * APAD + k + cg + 4]);
        qf[ks][3] = __float_as_uint(Ps[(wrow + g + 8) * APAD + k + cg + 4]);
    }
    __syncthreads();

    float o[8][4];
#pragma unroll
    for (int nj = 0; nj < 8; nj++)
#pragma unroll
        for (int e = 0; e < 4; e++) o[nj][e] = 0.f;
    float m0 = -1e30f, m1 = -1e30f, l0 = 0.f, l1 = 0.f;

    for (int k0 = 0; k0 < SEQ; k0 += AKV) {
        // Load K/V chunk
        for (int idx = tid; idx < AKV * HD / 2; idx += 256) {
            const int r = idx >> 5;
            const int c = (idx & 31) * 2;
            const size_t ro = base + (size_t)(k0 + r) * (3 * ETOT) + h * HD + c;
            const float2 kv = *(const float2*)(qkv + ro + ETOT);
            const float2 vv = *(const float2*)(qkv + ro + 2 * ETOT);
            Ks[r * APAD + c] = kv.x; Ks[r * APAD + c + 1] = kv.y;
            Vs[r * APAD + c] = vv.x; Vs[r * APAD + c + 1] = vv.y;
        }
        __syncthreads();

        // S = Q @ K^T
        float s[8][4];
#pragma unroll
        for (int nj = 0; nj < 8; nj++)
#pragma unroll
            for (int e = 0; e < 4; e++) s[nj][e] = 0.f;
#pragma unroll
        for (int ks = 0; ks < 8; ks++) {
            const int k = ks * 8;
            uint32_t bf[8][2];
#pragma unroll
            for (int nj = 0; nj < 8; nj++) {
                const int kr = nj * 8 + g;
                bf[nj][0] = __float_as_uint(Ks[kr * APAD + k + cg]);
                bf[nj][1] = __float_as_uint(Ks[kr * APAD + k + cg + 4]);
            }
#pragma unroll
            for (int nj = 0; nj < 8; nj++)
                mma_tf32(s[nj], qf[ks], bf[nj]);
        }

        // scale + online softmax (rows g / g+8; quad holds full 64-col rows)
        float mn0 = -1e30f, mn1 = -1e30f;
#pragma unroll
        for (int nj = 0; nj < 8; nj++) {
#pragma unroll
            for (int e = 0; e < 4; e++) s[nj][e] *= 0.125f;
            mn0 = fmaxf(mn0, fmaxf(s[nj][0], s[nj][1]));
            mn1 = fmaxf(mn1, fmaxf(s[nj][2], s[nj][3]));
        }
        mn0 = fmaxf(mn0, __shfl_xor_sync(0xffffffffu, mn0, 1));
        mn0 = fmaxf(mn0, __shfl_xor_sync(0xffffffffu, mn0, 2));
        mn1 = fmaxf(mn1, __shfl_xor_sync(0xffffffffu, mn1, 1));
        mn1 = fmaxf(mn1, __shfl_xor_sync(0xffffffffu, mn1, 2));
        const float mN0 = fmaxf(m0, mn0);
        const float mN1 = fmaxf(m1, mn1);
        const float c0 = __expf(m0 - mN0);
        const float c1 = __expf(m1 - mN1);
        m0 = mN0; m1 = mN1;
        float sum0 = 0.f, sum1 = 0.f;
#pragma unroll
        for (int nj = 0; nj < 8; nj++) {
            s[nj][0] = __expf(s[nj][0] - mN0);
            s[nj][1] = __expf(s[nj][1] - mN0);
            s[nj][2] = __expf(s[nj][2] - mN1);
            s[nj][3] = __expf(s[nj][3] - mN1);
            sum0 += s[nj][0] + s[nj][1];
            sum1 += s[nj][2] + s[nj][3];
        }
        sum0 += __shfl_xor_sync(0xffffffffu, sum0, 1);
        sum0 += __shfl_xor_sync(0xffffffffu, sum0, 2);
        sum1 += __shfl_xor_sync(0xffffffffu, sum1, 1);
        sum1 += __shfl_xor_sync(0xffffffffu, sum1, 2);
        l0 = l0 * c0 + sum0;
        l1 = l1 * c1 + sum1;
#pragma unroll
        for (int nj = 0; nj < 8; nj++) {
            o[nj][0] *= c0; o[nj][1] *= c0;
            o[nj][2] *= c1; o[nj][3] *= c1;
        }

        // Write P (tf32) to own warp's smem slab; only warp-local visibility needed
#pragma unroll
        for (int nj = 0; nj < 8; nj++) {
            const int n = nj * 8 + 2 * cg;
            Ps[(wrow + g)     * APAD + n]     = f2tf32f(s[nj][0]);
            Ps[(wrow + g)     * APAD + n + 1] = f2tf32f(s[nj][1]);
            Ps[(wrow + g + 8) * APAD + n]     = f2tf32f(s[nj][2]);
            Ps[(wrow + g + 8) * APAD + n + 1] = f2tf32f(s[nj][3]);
        }
        __syncwarp();

        // O += P @ V
#pragma unroll
        for (int ks = 0; ks < 8; ks++) {
            const int k = ks * 8;
            uint32_t pf[4];
            pf[0] = __float_as_uint(Ps[(wrow + g)     * APAD + k + cg]);
            pf[1] = __float_as_uint(Ps[(wrow + g + 8) * APAD + k + cg]);
            pf[2] = __float_as_uint(Ps[(wrow + g)     * APAD + k + cg + 4]);
            pf[3] = __float_as_uint(Ps[(wrow + g + 8) * APAD + k + cg + 4]);
#pragma unroll
            for (int nj = 0; nj < 8; nj++) {
                uint32_t bf[2];
                bf[0] = __float_as_uint(Vs[(k + cg)     * APAD + nj * 8 + g]);
                bf[1] = __float_as_uint(Vs[(k + cg + 4) * APAD + nj * 8 + g]);
                mma_tf32(o[nj], pf, bf);
            }
        }
        __syncthreads();   // before next chunk overwrites Ks/Vs
    }

    // Epilogue: normalize, round to tf32 (feeds GEMM4 A), write
    const float inv0 = 1.0f / l0;
    const float inv1 = 1.0f / l1;
    const int tokA = q0 + wrow + g;
    const int tokB = tokA + 8;
    const size_t rA = (size_t)(b * SEQ + tokA) * ETOT + h * HD;
    const size_t rB = (size_t)(b * SEQ + tokB) * ETOT + h * HD;
#pragma unroll
    for (int nj = 0; nj < 8; nj++) {
        const int n = nj * 8 + 2 * cg;
        float2 v0 = make_float2(f2tf32f(o[nj][0] * inv0), f2tf32f(o[nj][1] * inv0));
        float2 v1 = make_float2(f2tf32f(o[nj][2] * inv1), f2tf32f(o[nj][3] * inv1));
        *(float2*)(out + rA + n) = v0;
        *(float2*)(out + rB + n) = v1;
    }
}

// ---------------------------------------------------------------------------
// Host launcher
// ---------------------------------------------------------------------------
extern "C" void kernel_launch(void* const* d_in, const int* in_sizes, int n_in,
                              void* d_out, int out_size)
{
    const float* x     = (const float*)d_in[0];
    const float* qkv_w = (const float*)d_in[1];
    const float* fc_w  = (const float*)d_in[2];
    const float* fc_b  = (const float*)d_in[3];
    const float* ln1_g = (const float*)d_in[4];
    const float* ln1_b = (const float*)d_in[5];
    const float* ln2_g = (const float*)d_in[6];
    const float* ln2_b = (const float*)d_in[7];
    const float* w1    = (const float*)d_in[8];
    const float* b1    = (const float*)d_in[9];
    const float* w2    = (const float*)d_in[10];
    const float* b2    = (const float*)d_in[11];
    float* out = (float*)d_out;

    void *ph, *pq, *pa, *px2, *pm, *pwq, *pwf, *pw1, *pw2;
    cudaGetSymbolAddress(&ph,  g_h);
    cudaGetSymbolAddress(&pq,  g_qkv);
    cudaGetSymbolAddress(&pa,  g_attn);
    cudaGetSymbolAddress(&px2, g_x2);
    cudaGetSymbolAddress(&pm,  g_mid);
    cudaGetSymbolAddress(&pwq, g_wq);
    cudaGetSymbolAddress(&pwf, g_wf);
    cudaGetSymbolAddress(&pw1, g_w1);
    cudaGetSymbolAddress(&pw2, g_w2);
    float* h    = (float*)ph;
    float* qkvb = (float*)pq;
    float* attn = (float*)pa;
    float* x2   = (float*)px2;
    float* mid  = (float*)pm;
    float* wq   = (float*)pwq;
    float* wf   = (float*)pwf;
    float* w1r  = (float*)pw1;
    float* w2r  = (float*)pw2;

    cudaFuncSetAttribute(tc_gemm<false, false, false, true>,
                         cudaFuncAttributeMaxDynamicSharedMemorySize, SMEM_GEMM);
    cudaFuncSetAttribute(tc_gemm<true, true, false, false>,
                         cudaFuncAttributeMaxDynamicSharedMemorySize, SMEM_GEMM);
    cudaFuncSetAttribute(tc_gemm<true, false, true, true>,
                         cudaFuncAttributeMaxDynamicSharedMemorySize, SMEM_GEMM);
    cudaFuncSetAttribute(attn_mma,
                         cudaFuncAttributeMaxDynamicSharedMemorySize, SMEM_ATTN);

    // 0. Round weights to tf32 (once per launch)
    round_w<<<(3 * ETOT * ETOT / 4 + 255) / 256, 256>>>(qkv_w, wq, 3 * ETOT * ETOT / 4);
    round_w<<<(ETOT * ETOT / 4 + 255) / 256, 256>>>(fc_w, wf, ETOT * ETOT / 4);
    round_w<<<(MLPD * ETOT / 4 + 255) / 256, 256>>>(w1, w1r, MLPD * ETOT / 4);
    round_w<<<(ETOT * MLPD / 4 + 255) / 256, 256>>>(w2, w2r, ETOT * MLPD / 4);

    // 1. h = LN1(x)  (tf32-rounded)
    ln_kernel<<<NTOK, 256>>>(x, ln1_g, ln1_b, h);

    // 2. qkv = h @ qkv_w^T  (tf32-rounded output)
    tc_gemm<false, false, false, true>
        <<<dim3((3 * ETOT) / BN, NTOK / BM), 256, SMEM_GEMM>>>(
        h, wq, nullptr, nullptr, qkvb, NTOK, 3 * ETOT, ETOT);

    // 3. attention (tf32 mma, tf32-rounded output)
    attn_mma<<<dim3(SEQ / AQ, 4 * NH), 256, SMEM_ATTN>>>(qkvb, attn);

    // 4. x2 = x + attn @ fc_w^T + fc_b  (fp32 out)
    tc_gemm<true, true, false, false>
        <<<dim3(ETOT / BN, NTOK / BM), 256, SMEM_GEMM>>>(
        attn, wf, fc_b, x, x2, NTOK, ETOT, ETOT);

    // 5. h = LN2(x2)  (tf32-rounded)
    ln_kernel<<<NTOK, 256>>>(x2, ln2_g, ln2_b, h);

    // 6. mid = gelu(h @ w1^T + b1)  (tf32-rounded output)
    tc_gemm<true, false, true, true>
        <<<dim3(MLPD / BN, NTOK / BM), 256, SMEM_GEMM>>>(
        h, w1r, b1, nullptr, mid, NTOK, MLPD, ETOT);

    // 7. out = x2 + mid @ w2^T + b2  (fp32 out)
    tc_gemm<true, true, false, false>
        <<<dim3(ETOT / BN, NTOK / BM), 256, SMEM_GEMM>>>(
        mid, w2r, b2, x2, out, NTOK, ETOT, MLPD);
}